// round 10
// baseline (speedup 1.0000x reference)
#include <cuda_runtime.h>
#include <cuda_fp16.h>
#include <math.h>
#include <stdint.h>

// ---------------------------------------------------------------------------
// TT feed-forward via dense weight materialization + fp16 mma.sync GEMMs.
// GEMM1: f32 accumulate (precision anchor). GEMM2: f16 accumulate with
// promotion to f32 every 32 K (2 MMAs) -> ~2x tensor rate on sm_103 legacy HMMA.
//   W1t[4096,1024], W2t[1024,4096] (transposed, fp16)
//   Xh = half(x);  H = half(GELU(Xh @ W1t^T + b1));  out = H @ W2t^T + b2
// ---------------------------------------------------------------------------

__device__ float  g_P  [2][128 * 256 * 16];
__device__ __half g_W1t[4096 * 1024];
__device__ __half g_W2t[1024 * 4096];
__device__ __half g_H  [4096 * 4096];
__device__ __half g_Xh [4096 * 1024];

// ------------------------------ helpers -----------------------------------
__device__ __forceinline__ uint32_t smem_u32(const void* p) {
    uint32_t a;
    asm("{ .reg .u64 t; cvta.to.shared.u64 t, %1; cvt.u32.u64 %0, t; }"
        : "=r"(a) : "l"(p));
    return a;
}
__device__ __forceinline__ void cp16(uint32_t dst, const void* src) {
    asm volatile("cp.async.cg.shared.global [%0], [%1], 16;"
                 :: "r"(dst), "l"(src));
}
#define CP_COMMIT() asm volatile("cp.async.commit_group;")
#define CP_WAIT(n)  asm volatile("cp.async.wait_group %0;" :: "n"(n))

__device__ __forceinline__ void mma_f16(float c[4], const uint32_t a[4],
                                        const uint32_t b[2]) {
    asm volatile(
        "mma.sync.aligned.m16n8k16.row.col.f32.f16.f16.f32 "
        "{%0,%1,%2,%3}, {%4,%5,%6,%7}, {%8,%9}, {%0,%1,%2,%3};"
        : "+f"(c[0]), "+f"(c[1]), "+f"(c[2]), "+f"(c[3])
        : "r"(a[0]), "r"(a[1]), "r"(a[2]), "r"(a[3]), "r"(b[0]), "r"(b[1]));
}
__device__ __forceinline__ void mma_f16acc(uint32_t c[2], const uint32_t a[4],
                                           const uint32_t b[2]) {
    asm volatile(
        "mma.sync.aligned.m16n8k16.row.col.f16.f16.f16.f16 "
        "{%0,%1}, {%2,%3,%4,%5}, {%6,%7}, {%0,%1};"
        : "+r"(c[0]), "+r"(c[1])
        : "r"(a[0]), "r"(a[1]), "r"(a[2]), "r"(a[3]), "r"(b[0]), "r"(b[1]));
}
__device__ __forceinline__ void ldsm4(uint32_t& r0, uint32_t& r1,
                                      uint32_t& r2, uint32_t& r3,
                                      uint32_t addr) {
    asm volatile("ldmatrix.sync.aligned.m8n8.x4.shared.b16 {%0,%1,%2,%3}, [%4];"
                 : "=r"(r0), "=r"(r1), "=r"(r2), "=r"(r3) : "r"(addr));
}
__device__ __forceinline__ uint32_t pack2(float a, float b) {
    __half2 h = __floats2half2_rn(a, b);
    return *(uint32_t*)&h;
}
__device__ __forceinline__ void promote(float acc[4], uint32_t h0, uint32_t h1) {
    float2 fa = __half22float2(*(__half2*)&h0);
    float2 fb = __half22float2(*(__half2*)&h1);
    acc[0] += fa.x; acc[1] += fa.y; acc[2] += fb.x; acc[3] += fb.y;
}

// ----------------------- prep: xhalf + both pair contractions --------------
__global__ void prep_kernel(const float* __restrict__ x, uint4* __restrict__ xh,
                            const float* __restrict__ c10,
                            const float* __restrict__ c11,
                            const float* __restrict__ c20,
                            const float* __restrict__ c21) {
    int bid = blockIdx.x;
    if (bid < 2048) {
        int i = bid * 256 + threadIdx.x;      // 524288
        const float4* xv = (const float4*)x;
        float4 v0 = xv[2 * i], v1 = xv[2 * i + 1];
        uint4 r;
        r.x = pack2(v0.x, v0.y); r.y = pack2(v0.z, v0.w);
        r.z = pack2(v1.x, v1.y); r.w = pack2(v1.z, v1.w);
        xh[i] = r;
    } else {
        int b = bid - 2048;
        int half = b >> 9;
        int idx  = (b & 511) * 256 + threadIdx.x;   // 131072 per half
        const float* c0 = half ? c20 : c10;
        const float* c1 = half ? c21 : c11;
        int r2q  = idx & 3;
        int j    = (idx >> 2) & 255;
        int pair = idx >> 10;
        const float* c0p = c0 + pair * 16;
        float4 acc = make_float4(0, 0, 0, 0);
#pragma unroll
        for (int r1 = 0; r1 < 16; ++r1) {
            float w = c0p[r1];
            float4 v = ((const float4*)(c1 + (r1 * 256 + j) * 16))[r2q];
            acc.x += w * v.x; acc.y += w * v.y;
            acc.z += w * v.z; acc.w += w * v.w;
        }
        ((float4*)g_P[half])[idx] = acc;
    }
}

// ------------------------- weight materialization -------------------------
__global__ void weights_kernel(const float* __restrict__ c12,
                               const float* __restrict__ c22) {
    __shared__ float s[2048];
    int bid = blockIdx.x;
    if (bid < 2048) {
        // ---- W1t[m, n]: m hidden (16,16,16), n embed (8,16,8) ----
        for (int i = threadIdx.x; i < 2048; i += blockDim.x) {
            int r2 = i >> 7, n3 = (i >> 4) & 7, m3 = i & 15;   // c12:[r2][n3][m3]
            s[(r2 * 16 + m3) * 8 + n3] = c12[i];
        }
        __syncthreads();
        int idx = bid * 256 + threadIdx.x;    // 524288
        int nq = idx & 127;
        int m  = idx >> 7;
        int n1 = nq >> 4, n2 = nq & 15;
        int m1 = m >> 8, m2 = (m >> 4) & 15, m3 = m & 15;
        const float4* p4 = (const float4*)(g_P[0] +
            (((n1 * 16 + m1) * 256) + (n2 * 16 + m2)) * 16);
        float pv[16];
        *(float4*)&pv[0]  = p4[0]; *(float4*)&pv[4]  = p4[1];
        *(float4*)&pv[8]  = p4[2]; *(float4*)&pv[12] = p4[3];
        float acc[8] = {0, 0, 0, 0, 0, 0, 0, 0};
#pragma unroll
        for (int r2 = 0; r2 < 16; ++r2) {
            const float* sr = s + (r2 * 16 + m3) * 8;
#pragma unroll
            for (int j = 0; j < 8; ++j) acc[j] += pv[r2] * sr[j];
        }
        uint4 o;
        o.x = pack2(acc[0], acc[1]); o.y = pack2(acc[2], acc[3]);
        o.z = pack2(acc[4], acc[5]); o.w = pack2(acc[6], acc[7]);
        *(uint4*)(g_W1t + (size_t)m * 1024 + nq * 8) = o;
    } else {
        // ---- W2t[m, n]: m embed (8,16,8), n hidden (16,16,16) ----
        for (int i = threadIdx.x; i < 2048; i += blockDim.x) {
            int r2 = i >> 7, n3 = (i >> 3) & 15, m3 = i & 7;   // c22:[r2][n3][m3]
            s[(r2 * 8 + m3) * 16 + n3] = c22[i];
        }
        __syncthreads();
        int idx = (bid - 2048) * 256 + threadIdx.x;   // 524288
        int nh = idx & 511;
        int m  = idx >> 9;
        int n1 = nh >> 5, n2 = (nh >> 1) & 15, n3b = (nh & 1) * 8;
        int m1 = m >> 7, m2 = (m >> 3) & 15, m3 = m & 7;
        const float4* p4 = (const float4*)(g_P[1] +
            (((n1 * 8 + m1) * 256) + (n2 * 16 + m2)) * 16);
        float pv[16];
        *(float4*)&pv[0]  = p4[0]; *(float4*)&pv[4]  = p4[1];
        *(float4*)&pv[8]  = p4[2]; *(float4*)&pv[12] = p4[3];
        float acc[8] = {0, 0, 0, 0, 0, 0, 0, 0};
#pragma unroll
        for (int r2 = 0; r2 < 16; ++r2) {
            const float* sr = s + (r2 * 8 + m3) * 16 + n3b;
#pragma unroll
            for (int j = 0; j < 8; ++j) acc[j] += pv[r2] * sr[j];
        }
        uint4 o;
        o.x = pack2(acc[0], acc[1]); o.y = pack2(acc[2], acc[3]);
        o.z = pack2(acc[4], acc[5]); o.w = pack2(acc[6], acc[7]);
        *(uint4*)(g_W2t + (size_t)m * 4096 + nh * 8) = o;
    }
}

// --------------------------- GEMM1: f32 accumulate -------------------------
// H(half) = GELU(Xh @ W1t^T + b1).  CTA 128x128, 256 thr, warp 64x32, BK=64.
#define STAGE_B 32768

__global__ void __launch_bounds__(256, 2) gemm1_f32acc(
    const __half* __restrict__ A, const __half* __restrict__ B,
    const float* __restrict__ bias, __half* __restrict__ C,
    int K, int N) {
    extern __shared__ char smem[];
    uint32_t sb = smem_u32(smem);

    int tid  = threadIdx.x;
    int lane = tid & 31;
    int q    = lane & 3;
    int g8   = lane >> 2;
    int warp = tid >> 5;
    int wm   = (warp & 1) * 64;
    int wn   = (warp >> 1) * 32;

    size_t rowBase = (size_t)blockIdx.y * 128;
    size_t colBase = (size_t)blockIdx.x * 128;

    int r0 = tid >> 3, j0 = tid & 7;
    uint32_t stOff = (uint32_t)(r0 * 128 + ((j0 ^ (r0 & 7)) << 4));
    const __half* Asrc = A + (rowBase + r0) * (size_t)K + j0 * 8;
    const __half* Bsrc = B + (colBase + r0) * (size_t)K + j0 * 8;
    size_t strideR = (size_t)32 * K;

#define LOAD_STAGE(buf) do {                                                 \
    uint32_t stg_ = sb + (uint32_t)(buf) * STAGE_B;                          \
    _Pragma("unroll")                                                        \
    for (int i = 0; i < 4; ++i) {                                            \
        cp16(stg_ + stOff + (uint32_t)(i * 4096),         Asrc + i * strideR); \
        cp16(stg_ + 16384 + stOff + (uint32_t)(i * 4096), Bsrc + i * strideR); \
    }                                                                        \
    CP_COMMIT();                                                             \
    Asrc += 64; Bsrc += 64;                                                  \
} while (0)

    int rT  = lane & 15;
    int cT  = lane >> 4;
    int swz = lane & 7;
    uint32_t aB0 = (uint32_t)((wm + rT) * 128);
    uint32_t bB0 = (uint32_t)(16384 + (wn + rT) * 128);
    uint32_t xo[4];
#pragma unroll
    for (int ks = 0; ks < 4; ++ks)
        xo[ks] = ((((uint32_t)(ks * 2) + (uint32_t)cT) ^ (uint32_t)swz) << 4);

    float acc[4][4][4];
#pragma unroll
    for (int i = 0; i < 4; ++i)
#pragma unroll
        for (int j = 0; j < 4; ++j)
#pragma unroll
            for (int k = 0; k < 4; ++k) acc[i][j][k] = 0.f;

    int nS = K >> 6;
    LOAD_STAGE(0);
    LOAD_STAGE(1);

    int buf = 0;
    for (int s = 0; s < nS; ++s) {
        if (s + 2 < nS) CP_WAIT(1); else CP_WAIT(0);
        __syncthreads();
        if (s + 2 < nS) {
            int nb = buf - 1; if (nb < 0) nb += 3;
            LOAD_STAGE(nb);
        }

        uint32_t stg = sb + (uint32_t)buf * STAGE_B;
#pragma unroll
        for (int ks = 0; ks < 4; ++ks) {
            uint32_t af[4][4], bf[4][2];
#pragma unroll
            for (int mt = 0; mt < 4; ++mt)
                ldsm4(af[mt][0], af[mt][1], af[mt][2], af[mt][3],
                      stg + aB0 + (uint32_t)(mt * 2048) + xo[ks]);
#pragma unroll
            for (int p = 0; p < 2; ++p) {
                uint32_t t0, t1, t2, t3;
                ldsm4(t0, t1, t2, t3, stg + bB0 + (uint32_t)(p * 2048) + xo[ks]);
                bf[2 * p][0] = t0;     bf[2 * p][1] = t2;
                bf[2 * p + 1][0] = t1; bf[2 * p + 1][1] = t3;
            }
#pragma unroll
            for (int mt = 0; mt < 4; ++mt)
#pragma unroll
                for (int nt = 0; nt < 4; ++nt)
                    mma_f16(acc[mt][nt], af[mt], bf[nt]);
        }
        buf = (buf == 2) ? 0 : buf + 1;
    }

    // ---- epilogue: bias + exact-erf GELU -> half ----
#pragma unroll
    for (int nt = 0; nt < 4; ++nt) {
        int col = (int)colBase + wn + nt * 8 + 2 * q;
        float bx = bias[col], by = bias[col + 1];
#pragma unroll
        for (int mt = 0; mt < 4; ++mt) {
            size_t row0 = rowBase + wm + mt * 16 + g8;
            float v0 = acc[mt][nt][0] + bx;
            float v1 = acc[mt][nt][1] + by;
            float v2 = acc[mt][nt][2] + bx;
            float v3 = acc[mt][nt][3] + by;
            v0 = 0.5f * v0 * (1.0f + erff(v0 * 0.70710678118654752f));
            v1 = 0.5f * v1 * (1.0f + erff(v1 * 0.70710678118654752f));
            v2 = 0.5f * v2 * (1.0f + erff(v2 * 0.70710678118654752f));
            v3 = 0.5f * v3 * (1.0f + erff(v3 * 0.70710678118654752f));
            *(uint32_t*)&C[row0 * (size_t)N + col]       = pack2(v0, v1);
            *(uint32_t*)&C[(row0 + 8) * (size_t)N + col] = pack2(v2, v3);
        }
    }
#undef LOAD_STAGE
}

// ------------------- GEMM2: f16 accumulate, promote every 32K --------------
// out(float) = H @ W2t^T + b2.  Same chassis; per 32-K chunk: 2 f16-acc MMAs
// then promotion into f32 accumulators.
__global__ void __launch_bounds__(256, 2) gemm2_f16acc(
    const __half* __restrict__ A, const __half* __restrict__ B,
    const float* __restrict__ bias, float* __restrict__ C,
    int K, int N) {
    extern __shared__ char smem[];
    uint32_t sb = smem_u32(smem);

    int tid  = threadIdx.x;
    int lane = tid & 31;
    int q    = lane & 3;
    int g8   = lane >> 2;
    int warp = tid >> 5;
    int wm   = (warp & 1) * 64;
    int wn   = (warp >> 1) * 32;

    size_t rowBase = (size_t)blockIdx.y * 128;
    size_t colBase = (size_t)blockIdx.x * 128;

    int r0 = tid >> 3, j0 = tid & 7;
    uint32_t stOff = (uint32_t)(r0 * 128 + ((j0 ^ (r0 & 7)) << 4));
    const __half* Asrc = A + (rowBase + r0) * (size_t)K + j0 * 8;
    const __half* Bsrc = B + (colBase + r0) * (size_t)K + j0 * 8;
    size_t strideR = (size_t)32 * K;

#define LOAD_STAGE(buf) do {                                                 \
    uint32_t stg_ = sb + (uint32_t)(buf) * STAGE_B;                          \
    _Pragma("unroll")                                                        \
    for (int i = 0; i < 4; ++i) {                                            \
        cp16(stg_ + stOff + (uint32_t)(i * 4096),         Asrc + i * strideR); \
        cp16(stg_ + 16384 + stOff + (uint32_t)(i * 4096), Bsrc + i * strideR); \
    }                                                                        \
    CP_COMMIT();                                                             \
    Asrc += 64; Bsrc += 64;                                                  \
} while (0)

    int rT  = lane & 15;
    int cT  = lane >> 4;
    int swz = lane & 7;
    uint32_t aB0 = (uint32_t)((wm + rT) * 128);
    uint32_t bB0 = (uint32_t)(16384 + (wn + rT) * 128);
    uint32_t xo[4];
#pragma unroll
    for (int ks = 0; ks < 4; ++ks)
        xo[ks] = ((((uint32_t)(ks * 2) + (uint32_t)cT) ^ (uint32_t)swz) << 4);

    float acc[4][4][4];
#pragma unroll
    for (int i = 0; i < 4; ++i)
#pragma unroll
        for (int j = 0; j < 4; ++j)
#pragma unroll
            for (int k = 0; k < 4; ++k) acc[i][j][k] = 0.f;

    int nS = K >> 6;
    LOAD_STAGE(0);
    LOAD_STAGE(1);

    int buf = 0;
    for (int s = 0; s < nS; ++s) {
        if (s + 2 < nS) CP_WAIT(1); else CP_WAIT(0);
        __syncthreads();
        if (s + 2 < nS) {
            int nb = buf - 1; if (nb < 0) nb += 3;
            LOAD_STAGE(nb);
        }

        uint32_t stg = sb + (uint32_t)buf * STAGE_B;
#pragma unroll
        for (int p = 0; p < 2; ++p) {        // two 32-K chunks per 64-K stage
            uint32_t af2[2][4][4], bf2[2][4][2];
#pragma unroll
            for (int kk = 0; kk < 2; ++kk) {
                int ks = 2 * p + kk;
#pragma unroll
                for (int mt = 0; mt < 4; ++mt)
                    ldsm4(af2[kk][mt][0], af2[kk][mt][1],
                          af2[kk][mt][2], af2[kk][mt][3],
                          stg + aB0 + (uint32_t)(mt * 2048) + xo[ks]);
#pragma unroll
                for (int pp = 0; pp < 2; ++pp) {
                    uint32_t t0, t1, t2, t3;
                    ldsm4(t0, t1, t2, t3,
                          stg + bB0 + (uint32_t)(pp * 2048) + xo[ks]);
                    bf2[kk][2 * pp][0] = t0;     bf2[kk][2 * pp][1] = t2;
                    bf2[kk][2 * pp + 1][0] = t1; bf2[kk][2 * pp + 1][1] = t3;
                }
            }
#pragma unroll
            for (int mt = 0; mt < 4; ++mt)
#pragma unroll
                for (int nt = 0; nt < 4; ++nt) {
                    uint32_t h[2] = {0u, 0u};
                    mma_f16acc(h, af2[0][mt], bf2[0][nt]);
                    mma_f16acc(h, af2[1][mt], bf2[1][nt]);
                    promote(acc[mt][nt], h[0], h[1]);
                }
        }
        buf = (buf == 2) ? 0 : buf + 1;
    }

    // ---- epilogue: bias, float stores ----
#pragma unroll
    for (int nt = 0; nt < 4; ++nt) {
        int col = (int)colBase + wn + nt * 8 + 2 * q;
        float bx = bias[col], by = bias[col + 1];
#pragma unroll
        for (int mt = 0; mt < 4; ++mt) {
            size_t row0 = rowBase + wm + mt * 16 + g8;
            float v0 = acc[mt][nt][0] + bx;
            float v1 = acc[mt][nt][1] + by;
            float v2 = acc[mt][nt][2] + bx;
            float v3 = acc[mt][nt][3] + by;
            *(float2*)&C[row0 * (size_t)N + col]       = make_float2(v0, v1);
            *(float2*)&C[(row0 + 8) * (size_t)N + col] = make_float2(v2, v3);
        }
    }
#undef LOAD_STAGE
}

// --------------------------------- launch ---------------------------------
extern "C" void kernel_launch(void* const* d_in, const int* in_sizes, int n_in,
                              void* d_out, int out_size) {
    const float* x   = (const float*)d_in[0];
    const float* c10 = (const float*)d_in[1];
    const float* c11 = (const float*)d_in[2];
    const float* c12 = (const float*)d_in[3];
    const float* b1  = (const float*)d_in[4];
    const float* c20 = (const float*)d_in[5];
    const float* c21 = (const float*)d_in[6];
    const float* c22 = (const float*)d_in[7];
    const float* b2  = (const float*)d_in[8];
    float* out = (float*)d_out;

    __half *pW1t, *pW2t, *pH, *pXh;
    cudaGetSymbolAddress((void**)&pW1t, g_W1t);
    cudaGetSymbolAddress((void**)&pW2t, g_W2t);
    cudaGetSymbolAddress((void**)&pH,   g_H);
    cudaGetSymbolAddress((void**)&pXh,  g_Xh);

    const int SMEM = 3 * STAGE_B;   // 98304
    cudaFuncSetAttribute(gemm1_f32acc,
                         cudaFuncAttributeMaxDynamicSharedMemorySize, SMEM);
    cudaFuncSetAttribute(gemm2_f16acc,
                         cudaFuncAttributeMaxDynamicSharedMemorySize, SMEM);

    prep_kernel<<<3072, 256>>>(x, (uint4*)pXh, c10, c11, c20, c21);
    weights_kernel<<<4096, 256>>>(c12, c22);

    // GEMM1: H = half(GELU(Xh @ W1t^T + b1))   grid 32x32, f32 accumulate
    gemm1_f32acc<<<dim3(32, 32), 256, SMEM>>>(pXh, pW1t, b1, pH, 1024, 4096);
    // GEMM2: out = H @ W2t^T + b2              grid 8x32, f16acc + promote
    gemm2_f16acc<<<dim3(8, 32), 256, SMEM>>>(pH, pW2t, b2, out, 4096, 1024);
}

// round 11
// speedup vs baseline: 1.2734x; 1.2734x over previous
#include <cuda_runtime.h>
#include <cuda_fp16.h>
#include <math.h>
#include <stdint.h>

// ---------------------------------------------------------------------------
// TT feed-forward via dense weight materialization + fp16 mma.sync GEMMs
// (fp32 accumulate). CTA 128x128, warp 64x32, BK=64 halves, 3-stage cp.async,
// SW128 swizzle, ldmatrix.x4 fragments. (= proven R6 GEMM engine)
// Aux rebuilt: fused prep (x->half + pair contractions), low-traffic weights
// kernel (1 g_P row -> 128 outputs per thread).
// ---------------------------------------------------------------------------

__device__ float  g_P  [2][128 * 256 * 16];
__device__ __half g_W1t[4096 * 1024];
__device__ __half g_W2t[1024 * 4096];
__device__ __half g_H  [4096 * 4096];
__device__ __half g_Xh [4096 * 1024];

// ------------------------------ helpers -----------------------------------
__device__ __forceinline__ uint32_t smem_u32(const void* p) {
    uint32_t a;
    asm("{ .reg .u64 t; cvta.to.shared.u64 t, %1; cvt.u32.u64 %0, t; }"
        : "=r"(a) : "l"(p));
    return a;
}
__device__ __forceinline__ void cp16(uint32_t dst, const void* src) {
    asm volatile("cp.async.cg.shared.global [%0], [%1], 16;"
                 :: "r"(dst), "l"(src));
}
#define CP_COMMIT() asm volatile("cp.async.commit_group;")
#define CP_WAIT(n)  asm volatile("cp.async.wait_group %0;" :: "n"(n))

__device__ __forceinline__ void mma_f16(float c[4], const uint32_t a[4],
                                        const uint32_t b[2]) {
    asm volatile(
        "mma.sync.aligned.m16n8k16.row.col.f32.f16.f16.f32 "
        "{%0,%1,%2,%3}, {%4,%5,%6,%7}, {%8,%9}, {%0,%1,%2,%3};"
        : "+f"(c[0]), "+f"(c[1]), "+f"(c[2]), "+f"(c[3])
        : "r"(a[0]), "r"(a[1]), "r"(a[2]), "r"(a[3]), "r"(b[0]), "r"(b[1]));
}
__device__ __forceinline__ void ldsm4(uint32_t& r0, uint32_t& r1,
                                      uint32_t& r2, uint32_t& r3,
                                      uint32_t addr) {
    asm volatile("ldmatrix.sync.aligned.m8n8.x4.shared.b16 {%0,%1,%2,%3}, [%4];"
                 : "=r"(r0), "=r"(r1), "=r"(r2), "=r"(r3) : "r"(addr));
}
__device__ __forceinline__ uint32_t pack2(float a, float b) {
    __half2 h = __floats2half2_rn(a, b);
    return *(uint32_t*)&h;
}

// ----------------------- prep: xhalf + both pair contractions --------------
// blocks [0,2048): x -> half.  blocks [2048,3072): pair contraction.
__global__ void prep_kernel(const float* __restrict__ x, uint4* __restrict__ xh,
                            const float* __restrict__ c10,
                            const float* __restrict__ c11,
                            const float* __restrict__ c20,
                            const float* __restrict__ c21) {
    int bid = blockIdx.x;
    if (bid < 2048) {
        int i = bid * 256 + threadIdx.x;      // 524288
        const float4* xv = (const float4*)x;
        float4 v0 = xv[2 * i], v1 = xv[2 * i + 1];
        uint4 r;
        r.x = pack2(v0.x, v0.y); r.y = pack2(v0.z, v0.w);
        r.z = pack2(v1.x, v1.y); r.w = pack2(v1.z, v1.w);
        xh[i] = r;
    } else {
        int b = bid - 2048;
        int half = b >> 9;
        int idx  = (b & 511) * 256 + threadIdx.x;   // 131072 per half
        const float* c0 = half ? c20 : c10;
        const float* c1 = half ? c21 : c11;
        int r2q  = idx & 3;
        int j    = (idx >> 2) & 255;
        int pair = idx >> 10;
        const float* c0p = c0 + pair * 16;
        float4 acc = make_float4(0, 0, 0, 0);
#pragma unroll
        for (int r1 = 0; r1 < 16; ++r1) {
            float w = c0p[r1];
            float4 v = ((const float4*)(c1 + (r1 * 256 + j) * 16))[r2q];
            acc.x += w * v.x; acc.y += w * v.y;
            acc.z += w * v.z; acc.w += w * v.w;
        }
        ((float4*)g_P[half])[idx] = acc;
    }
}

// ------------------- weights v2: 128 outputs per thread --------------------
// blocks [0,128): W1t.  blocks [128,256): W2t.  One g_P row per thread.
__global__ void weights_kernel(const float* __restrict__ c12,
                               const float* __restrict__ c22) {
    __shared__ float s[2048];
    int bid = blockIdx.x;
    int tid = threadIdx.x;
    if (bid < 128) {
        // ---- W1t[m, n]: m hidden (m1,m2,m3 = 16,16,16), n embed (8,16,8) --
        // s[(r2*16+m3)*8+n3] = c12[r2*128 + n3*16 + m3]
        for (int i = tid; i < 2048; i += 256) {
            int r2 = i >> 7, n3 = (i >> 4) & 7, m3 = i & 15;
            s[(r2 * 16 + m3) * 8 + n3] = c12[i];
        }
        __syncthreads();
        int t  = bid * 256 + tid;          // 32768
        int nq = t & 127;                  // n1*16+n2
        int mq = t >> 7;                   // m1*16+m2
        int n1 = nq >> 4, n2 = nq & 15;
        int m1 = mq >> 4, m2 = mq & 15;
        const float4* p4 = (const float4*)(g_P[0] +
            (((n1 * 16 + m1) * 256) + (n2 * 16 + m2)) * 16);
        float pv[16];
        *(float4*)&pv[0]  = p4[0]; *(float4*)&pv[4]  = p4[1];
        *(float4*)&pv[8]  = p4[2]; *(float4*)&pv[12] = p4[3];
        for (int m3 = 0; m3 < 16; ++m3) {
            float acc[8] = {0, 0, 0, 0, 0, 0, 0, 0};
#pragma unroll
            for (int r2 = 0; r2 < 16; ++r2) {
                const float* sr = s + (r2 * 16 + m3) * 8;
#pragma unroll
                for (int j = 0; j < 8; ++j) acc[j] += pv[r2] * sr[j];
            }
            uint4 o;
            o.x = pack2(acc[0], acc[1]); o.y = pack2(acc[2], acc[3]);
            o.z = pack2(acc[4], acc[5]); o.w = pack2(acc[6], acc[7]);
            *(uint4*)(g_W1t + (size_t)(mq * 16 + m3) * 1024 + nq * 8) = o;
        }
    } else {
        // ---- W2t[m, n]: m embed (8,16,8), n hidden (16,16,16) ------------
        // s[(r2*8+m3)*16+n3] = c22[r2*128 + n3*8 + m3]
        for (int i = tid; i < 2048; i += 256) {
            int r2 = i >> 7, n3 = (i >> 3) & 15, m3 = i & 7;
            s[(r2 * 8 + m3) * 16 + n3] = c22[i];
        }
        __syncthreads();
        int t  = (bid - 128) * 256 + tid;  // 32768
        int nq = t & 255;                  // n1*16+n2
        int mq = t >> 8;                   // m1*16+m2  (m1<8)
        int n1 = nq >> 4, n2 = nq & 15;
        int m1 = mq >> 4, m2 = mq & 15;
        const float4* p4 = (const float4*)(g_P[1] +
            (((n1 * 8 + m1) * 256) + (n2 * 16 + m2)) * 16);
        float pv[16];
        *(float4*)&pv[0]  = p4[0]; *(float4*)&pv[4]  = p4[1];
        *(float4*)&pv[8]  = p4[2]; *(float4*)&pv[12] = p4[3];
        for (int m3 = 0; m3 < 8; ++m3) {
            float acc[16];
#pragma unroll
            for (int j = 0; j < 16; ++j) acc[j] = 0.f;
#pragma unroll
            for (int r2 = 0; r2 < 16; ++r2) {
                const float* sr = s + (r2 * 8 + m3) * 16;
#pragma unroll
                for (int j = 0; j < 16; ++j) acc[j] += pv[r2] * sr[j];
            }
            uint4 o0, o1;
            o0.x = pack2(acc[0],  acc[1]);  o0.y = pack2(acc[2],  acc[3]);
            o0.z = pack2(acc[4],  acc[5]);  o0.w = pack2(acc[6],  acc[7]);
            o1.x = pack2(acc[8],  acc[9]);  o1.y = pack2(acc[10], acc[11]);
            o1.z = pack2(acc[12], acc[13]); o1.w = pack2(acc[14], acc[15]);
            uint4* op = (uint4*)(g_W2t + (size_t)(mq * 8 + m3) * 4096 + nq * 16);
            op[0] = o0; op[1] = o1;
        }
    }
}

// ------------------------------- fp16 GEMM (R6) -----------------------------
// C[M,N] = A[M,K] * B[N,K]^T + bias.  fuse=1: C(half)=GELU(.), else C float.
#define STAGE_B 32768

__global__ void __launch_bounds__(256, 2) gemm_f16(
    const __half* __restrict__ A, const __half* __restrict__ B,
    const float* __restrict__ bias, void* __restrict__ Cv,
    int K, int N, int fuse) {
    extern __shared__ char smem[];
    uint32_t sb = smem_u32(smem);

    int tid  = threadIdx.x;
    int lane = tid & 31;
    int q    = lane & 3;
    int g8   = lane >> 2;
    int warp = tid >> 5;
    int wm   = (warp & 1) * 64;
    int wn   = (warp >> 1) * 32;

    size_t rowBase = (size_t)blockIdx.y * 128;
    size_t colBase = (size_t)blockIdx.x * 128;
    const __half* Ag = A + rowBase * (size_t)K;
    const __half* Bg = B + colBase * (size_t)K;

#define LOAD_STAGE(s, buf) do {                                              \
    uint32_t stg_ = sb + (uint32_t)(buf) * STAGE_B;                          \
    size_t koff = (size_t)(s) * 64;                                          \
    _Pragma("unroll")                                                        \
    for (int i = 0; i < 4; ++i) {                                            \
        int id = tid + 256 * i;                                              \
        int r = id >> 3, j = id & 7;                                         \
        uint32_t off = (uint32_t)(r * 128 + ((j ^ (r & 7)) << 4));           \
        cp16(stg_ + off,         Ag + (size_t)r * K + koff + j * 8);         \
        cp16(stg_ + 16384 + off, Bg + (size_t)r * K + koff + j * 8);         \
    }                                                                        \
    CP_COMMIT();                                                             \
} while (0)

    int rT  = lane & 15;
    int cT  = lane >> 4;
    int swz = lane & 7;
    uint32_t aB0 = (uint32_t)((wm + rT) * 128);
    uint32_t bB0 = (uint32_t)(16384 + (wn + rT) * 128);
    uint32_t xo[4];
#pragma unroll
    for (int ks = 0; ks < 4; ++ks)
        xo[ks] = ((((uint32_t)(ks * 2) + (uint32_t)cT) ^ (uint32_t)swz) << 4);

    float acc[4][4][4];
#pragma unroll
    for (int i = 0; i < 4; ++i)
#pragma unroll
        for (int j = 0; j < 4; ++j)
#pragma unroll
            for (int k = 0; k < 4; ++k) acc[i][j][k] = 0.f;

    int nS = K >> 6;
    LOAD_STAGE(0, 0);
    LOAD_STAGE(1, 1);

    int buf = 0;
    for (int s = 0; s < nS; ++s) {
        if (s + 2 < nS) CP_WAIT(1); else CP_WAIT(0);
        __syncthreads();
        if (s + 2 < nS) {
            int nb = buf - 1; if (nb < 0) nb += 3;
            LOAD_STAGE(s + 2, nb);
        }

        uint32_t stg = sb + (uint32_t)buf * STAGE_B;
#pragma unroll
        for (int ks = 0; ks < 4; ++ks) {
            uint32_t af[4][4], bf[4][2];
#pragma unroll
            for (int mt = 0; mt < 4; ++mt)
                ldsm4(af[mt][0], af[mt][1], af[mt][2], af[mt][3],
                      stg + aB0 + (uint32_t)(mt * 2048) + xo[ks]);
#pragma unroll
            for (int p = 0; p < 2; ++p) {
                uint32_t t0, t1, t2, t3;
                ldsm4(t0, t1, t2, t3, stg + bB0 + (uint32_t)(p * 2048) + xo[ks]);
                bf[2 * p][0] = t0;     bf[2 * p][1] = t2;
                bf[2 * p + 1][0] = t1; bf[2 * p + 1][1] = t3;
            }
#pragma unroll
            for (int mt = 0; mt < 4; ++mt)
#pragma unroll
                for (int nt = 0; nt < 4; ++nt)
                    mma_f16(acc[mt][nt], af[mt], bf[nt]);
        }
        buf = (buf == 2) ? 0 : buf + 1;
    }

    // ---- epilogue ----
#pragma unroll
    for (int nt = 0; nt < 4; ++nt) {
        int col = (int)colBase + wn + nt * 8 + 2 * q;
        float bx = bias[col], by = bias[col + 1];
#pragma unroll
        for (int mt = 0; mt < 4; ++mt) {
            size_t row0 = rowBase + wm + mt * 16 + g8;
            float v0 = acc[mt][nt][0] + bx;
            float v1 = acc[mt][nt][1] + by;
            float v2 = acc[mt][nt][2] + bx;
            float v3 = acc[mt][nt][3] + by;
            if (fuse) {
                v0 = 0.5f * v0 * (1.0f + erff(v0 * 0.70710678118654752f));
                v1 = 0.5f * v1 * (1.0f + erff(v1 * 0.70710678118654752f));
                v2 = 0.5f * v2 * (1.0f + erff(v2 * 0.70710678118654752f));
                v3 = 0.5f * v3 * (1.0f + erff(v3 * 0.70710678118654752f));
                __half* C = (__half*)Cv;
                *(uint32_t*)&C[row0 * (size_t)N + col]       = pack2(v0, v1);
                *(uint32_t*)&C[(row0 + 8) * (size_t)N + col] = pack2(v2, v3);
            } else {
                float* C = (float*)Cv;
                *(float2*)&C[row0 * (size_t)N + col]       = make_float2(v0, v1);
                *(float2*)&C[(row0 + 8) * (size_t)N + col] = make_float2(v2, v3);
            }
        }
    }
#undef LOAD_STAGE
}

// --------------------------------- launch ---------------------------------
extern "C" void kernel_launch(void* const* d_in, const int* in_sizes, int n_in,
                              void* d_out, int out_size) {
    const float* x   = (const float*)d_in[0];
    const float* c10 = (const float*)d_in[1];
    const float* c11 = (const float*)d_in[2];
    const float* c12 = (const float*)d_in[3];
    const float* b1  = (const float*)d_in[4];
    const float* c20 = (const float*)d_in[5];
    const float* c21 = (const float*)d_in[6];
    const float* c22 = (const float*)d_in[7];
    const float* b2  = (const float*)d_in[8];
    float* out = (float*)d_out;

    __half *pW1t, *pW2t, *pH, *pXh;
    cudaGetSymbolAddress((void**)&pW1t, g_W1t);
    cudaGetSymbolAddress((void**)&pW2t, g_W2t);
    cudaGetSymbolAddress((void**)&pH,   g_H);
    cudaGetSymbolAddress((void**)&pXh,  g_Xh);

    const int SMEM = 3 * STAGE_B;   // 98304
    cudaFuncSetAttribute(gemm_f16, cudaFuncAttributeMaxDynamicSharedMemorySize,
                         SMEM);

    prep_kernel<<<3072, 256>>>(x, (uint4*)pXh, c10, c11, c20, c21);
    weights_kernel<<<256, 256>>>(c12, c22);

    // GEMM1: H = half(GELU(Xh @ W1t^T + b1))   grid 32x32
    gemm_f16<<<dim3(32, 32), 256, SMEM>>>(pXh, pW1t, b1, pH, 1024, 4096, 1);
    // GEMM2: out = H @ W2t^T + b2              grid 8x32
    gemm_f16<<<dim3(8, 32), 256, SMEM>>>(pH, pW2t, b2, out, 4096, 1024, 0);
}